// round 10
// baseline (speedup 1.0000x reference)
#include <cuda_runtime.h>
#include <cuda_bf16.h>
#include <math.h>
#include <stdint.h>

#define B_  8
#define CIN 64
#define H_  128
#define W_  128
#define HO  64
#define WO  128
#define CO  64
#define HW_ (H_*W_)

// Scratch (no allocations allowed -> __device__ globals)
__device__ float g_bias[32];
__device__ __align__(16) char g_Wsplit[9*16384];   // deform W: per tap hi 8KB + lo 8KB, SW128
__device__ __align__(16) char g_WomSplit[9*8192];  // conv W: per tap hi 4KB + lo 4KB, SW128
__device__ __align__(16) float g_xT[(size_t)B_*H_*W_*CIN];  // NHWC transpose of x (32MB)

__device__ __forceinline__ uint32_t smem_u32(const void* p) {
    uint32_t a;
    asm("{ .reg .u64 t; cvta.to.shared.u64 t, %1; cvt.u32.u64 %0, t; }" : "=r"(a) : "l"(p));
    return a;
}
__device__ __forceinline__ uint32_t sw128(uint32_t off) { return off ^ ((off >> 3) & 0x70); }

#define LDMATRIX_X4(r0,r1,r2,r3,addr) \
    asm volatile("ldmatrix.sync.aligned.m8n8.x4.shared.b16 {%0,%1,%2,%3}, [%4];" \
                 : "=r"(r0),"=r"(r1),"=r"(r2),"=r"(r3) : "r"(addr))
#define LDMATRIX_X2(r0,r1,addr) \
    asm volatile("ldmatrix.sync.aligned.m8n8.x2.shared.b16 {%0,%1}, [%2];" \
                 : "=r"(r0),"=r"(r1) : "r"(addr))

#define MMA_BF16(c, a0,a1,a2,a3, b0,b1) \
    asm volatile("mma.sync.aligned.m16n8k16.row.col.f32.bf16.bf16.f32 " \
                 "{%0,%1,%2,%3},{%4,%5,%6,%7},{%8,%9},{%0,%1,%2,%3};" \
                 : "+f"((c)[0]),"+f"((c)[1]),"+f"((c)[2]),"+f"((c)[3]) \
                 : "r"(a0),"r"(a1),"r"(a2),"r"(a3), "r"(b0),"r"(b1))

#define CP16(dst, src) \
    asm volatile("cp.async.cg.shared.global [%0], [%1], 16;" :: "r"(dst), "l"(src) : "memory")
#define CP_COMMIT() asm volatile("cp.async.commit_group;" ::: "memory")
#define CP_WAIT(n)  asm volatile("cp.async.wait_group %0;" :: "n"(n) : "memory")

// bf16 hi/lo split of (v0, v1) -> packed hi word + packed lo word
#define SPLIT2(v0, v1, h, lw) do { \
    asm("cvt.rn.bf16x2.f32 %0, %1, %2;" : "=r"(h) : "f"(v1), "f"(v0)); \
    float _h0 = __uint_as_float((h) << 16); \
    float _h1 = __uint_as_float((h) & 0xffff0000u); \
    float _l0 = (v0) - _h0, _l1 = (v1) - _h1; \
    asm("cvt.rn.bf16x2.f32 %0, %1, %2;" : "=r"(lw) : "f"(_l1), "f"(_l0)); \
} while (0)

// ---------------------------------------------------------------------------
// Kernel 0: weight repack (hi/lo split, SW128 swizzled)
// ---------------------------------------------------------------------------
__global__ void prep_kernel(const float* __restrict__ w_off, const float* __restrict__ b_off,
                            const float* __restrict__ w_mask, const float* __restrict__ b_mask,
                            const float* __restrict__ w_conv) {
    int idx = blockIdx.x * blockDim.x + threadIdx.x;
    if (idx < 9*64*64) {
        int k = idx / 4096; int r = idx & 4095; int o = r >> 6; int c = r & 63;
        float w = w_conv[(o*64 + c)*9 + k];
        __nv_bfloat16 hi = __float2bfloat16(w);
        __nv_bfloat16 lo = __float2bfloat16(w - __bfloat162float(hi));
        uint32_t sw = sw128((uint32_t)(o*128 + c*2));
        *(__nv_bfloat16*)(g_Wsplit + k*16384 + sw)        = hi;
        *(__nv_bfloat16*)(g_Wsplit + k*16384 + 8192 + sw) = lo;
    }
    if (idx < 9*32*64) {
        int k = idx / 2048; int r = idx & 2047; int o = r >> 6; int c = r & 63;
        float w = 0.f;
        if (o < 18)       w = w_off[(o*64 + c)*9 + k];
        else if (o < 27)  w = w_mask[((o-18)*64 + c)*9 + k];
        __nv_bfloat16 hi = __float2bfloat16(w);
        __nv_bfloat16 lo = __float2bfloat16(w - __bfloat162float(hi));
        uint32_t sw = sw128((uint32_t)(o*128 + c*2));
        *(__nv_bfloat16*)(g_WomSplit + k*8192 + sw)        = hi;
        *(__nv_bfloat16*)(g_WomSplit + k*8192 + 4096 + sw) = lo;
    }
    if (idx < 32) {
        float v = 0.f;
        if (idx < 18)      v = b_off[idx];
        else if (idx < 27) v = b_mask[idx - 18];
        g_bias[idx] = v;
    }
}

// ---------------------------------------------------------------------------
// Kernel 0b: NCHW -> NHWC transpose of x
// ---------------------------------------------------------------------------
__global__ void __launch_bounds__(256) transpose_kernel(const float* __restrict__ x) {
    __shared__ float t[64][33];
    int x0 = blockIdx.x * 32, y = blockIdx.y, b = blockIdx.z;
    int tx = threadIdx.x & 31, tc = threadIdx.x >> 5;
    const float* xb = x + (size_t)b * CIN * HW_ + y*W_ + x0;
    #pragma unroll
    for (int cc = 0; cc < 8; ++cc)
        t[tc + cc*8][tx] = __ldg(xb + (size_t)(tc + cc*8)*HW_ + tx);
    __syncthreads();
    float* dst = g_xT + ((size_t)b*HW_ + y*W_ + x0) * CIN;
    int c = threadIdx.x & 63, xx = threadIdx.x >> 6;
    #pragma unroll
    for (int q = 0; q < 8; ++q)
        dst[(size_t)(xx + q*4)*CIN + c] = t[c][xx + q*4];
}

// ---------------------------------------------------------------------------
// Fused kernel: 64px x 64o tiles, 3 CTAs/SM target.
// ---------------------------------------------------------------------------
#define SM_A     0          // A: hi 8KB [0,8192), lo [8192,16384)
#define SM_W     16384      // W single buffer 16KB (phase1 uses hi@0/lo@4096)
#define SM_META  32768      // 2 x 64px x 32B = 4KB
#define SM_SOM   36864      // som[64 px][32 floats] = 8192
#define SM_TOTAL 45056

__global__ void __launch_bounds__(256, 3) deform_kernel(const float* __restrict__ x,
                                                        float* __restrict__ out) {
    extern __shared__ char sm[];
    const uint32_t smb = smem_u32(sm);
    int tid = threadIdx.x;
    int l = tid & 31, w = tid >> 5;
    int ho = blockIdx.x, b = blockIdx.y;
    int wo0 = blockIdx.z * 64;
    const float* xb = x + (size_t)b * CIN * HW_;

    int m2 = w & 1;                  // px 32-half (2 m16 tiles)
    int n4 = w >> 1;                 // phase-2: o tile base n4*16 (2 n8)

    // ---- ldmatrix lane offsets, per-ks (sw128 must wrap the full offset) ----
    uint32_t aoff[2][4], boff[4], b1off[4];
    {
        int arow = m2*32 + (l & 15);
        int acol = (l & 16) ? 16 : 0;
        #pragma unroll
        for (int ks = 0; ks < 4; ++ks) {
            aoff[0][ks] = sw128((uint32_t)(arow*128 + ks*32 + acol));
            aoff[1][ks] = sw128((uint32_t)((arow+16)*128 + ks*32 + acol));
        }
        int brow = n4*16 + (l & 7) + ((l & 16) ? 8 : 0);
        int bcol = (l & 8) ? 16 : 0;
        #pragma unroll
        for (int ks = 0; ks < 4; ++ks)
            boff[ks] = sw128((uint32_t)(brow*128 + ks*32 + bcol));
        int b1row = n4*8 + (l & 7);
        int b1col = ((l >> 3) & 1) ? 16 : 0;
        #pragma unroll
        for (int ks = 0; ks < 4; ++ks)
            b1off[ks] = sw128((uint32_t)(b1row*128 + ks*32 + b1col));
    }

    // ================= PHASE 1: offset/mask conv (64px x 32o) =================
    float acc1[2][4];
    #pragma unroll
    for (int m = 0; m < 2; ++m)
        #pragma unroll
        for (int r = 0; r < 4; ++r) acc1[m][r] = 0.f;

    int p1px = tid & 63, p1q = tid >> 6;     // A-build: px + 16-ch chunk

    #pragma unroll 1
    for (int k = 0; k < 9; ++k) {
        if (k) __syncthreads();
        // stage Wom(k) (single buffer; latency hidden under A build)
        {
            uint32_t dst = smb + SM_W + tid*16;
            const char* src = g_WomSplit + k*8192 + tid*16;
            CP16(dst, src); CP16(dst + 4096u, src + 4096);
            CP_COMMIT();
        }
        // build A_k[64px][64c] (NCHW coalesced)
        {
            int gy = 2*ho - 1 + (k/3);
            int gx = wo0 + p1px - 1 + (k%3);
            bool vld = (gy >= 0) && (gx >= 0) && (gx < W_);
            const float* xc = xb + (size_t)(p1q*16) * HW_ + gy*W_ + gx;
            uint32_t hv[8], lv[8];
            #pragma unroll
            for (int j = 0; j < 8; ++j) {
                float v0 = vld ? __ldg(xc)       : 0.f;
                float v1 = vld ? __ldg(xc + HW_) : 0.f;
                xc += 2*HW_;
                SPLIT2(v0, v1, hv[j], lv[j]);
            }
            uint32_t s0 = sw128((uint32_t)(p1px*128 + p1q*32));
            uint32_t s1 = sw128((uint32_t)(p1px*128 + p1q*32 + 16));
            *(uint4*)(sm + SM_A + s0)        = make_uint4(hv[0],hv[1],hv[2],hv[3]);
            *(uint4*)(sm + SM_A + s1)        = make_uint4(hv[4],hv[5],hv[6],hv[7]);
            *(uint4*)(sm + SM_A + 8192 + s0) = make_uint4(lv[0],lv[1],lv[2],lv[3]);
            *(uint4*)(sm + SM_A + 8192 + s1) = make_uint4(lv[4],lv[5],lv[6],lv[7]);
        }
        CP_WAIT(0);
        __syncthreads();
        // GEMM1: 2 m16 x 1 n8, 3 passes
        #pragma unroll
        for (int ks = 0; ks < 4; ++ks) {
            uint32_t ah[2][4], al[2][4], bh0,bh1, bl0,bl1;
            LDMATRIX_X4(ah[0][0],ah[0][1],ah[0][2],ah[0][3], smb + SM_A + aoff[0][ks]);
            LDMATRIX_X4(ah[1][0],ah[1][1],ah[1][2],ah[1][3], smb + SM_A + aoff[1][ks]);
            LDMATRIX_X4(al[0][0],al[0][1],al[0][2],al[0][3], smb + SM_A + 8192u + aoff[0][ks]);
            LDMATRIX_X4(al[1][0],al[1][1],al[1][2],al[1][3], smb + SM_A + 8192u + aoff[1][ks]);
            LDMATRIX_X2(bh0,bh1, smb + SM_W + b1off[ks]);
            LDMATRIX_X2(bl0,bl1, smb + SM_W + 4096u + b1off[ks]);
            #pragma unroll
            for (int m = 0; m < 2; ++m) {
                MMA_BF16(acc1[m], ah[m][0],ah[m][1],ah[m][2],ah[m][3], bh0, bh1);
                MMA_BF16(acc1[m], al[m][0],al[m][1],al[m][2],al[m][3], bh0, bh1);
                MMA_BF16(acc1[m], ah[m][0],ah[m][1],ah[m][2],ah[m][3], bl0, bl1);
            }
        }
    }

    // scatter som[px][o] = acc + bias (pitch 32)
    {
        float* som = (float*)(sm + SM_SOM);
        int g = l >> 2, tg = l & 3;
        int o = n4*8 + 2*tg;
        #pragma unroll
        for (int m = 0; m < 2; ++m) {
            int pa = m2*32 + m*16 + g;
            som[pa*32 + o]       = acc1[m][0] + g_bias[o];
            som[pa*32 + o + 1]   = acc1[m][1] + g_bias[o+1];
            som[(pa+8)*32 + o]   = acc1[m][2] + g_bias[o];
            som[(pa+8)*32 + o+1] = acc1[m][3] + g_bias[o+1];
        }
    }
    __syncthreads();

    // ================= PHASE 2: gather + deform GEMM (64px x 64o) =============
    #define META_FROM_SOM(TAP, BUF) do { \
        if (tid < 64) { \
            int px = tid; \
            const float* som = (const float*)(sm + SM_SOM); \
            float offy = som[px*32 + 2*(TAP)]; \
            float offx = som[px*32 + 2*(TAP) + 1]; \
            float mr   = som[px*32 + 18 + (TAP)]; \
            float mk   = 1.f / (1.f + expf(-mr)); \
            float py  = offy + (float)((TAP)/3) + (float)(2*ho - 1); \
            float pxx = offx + (float)((TAP)%3) + (float)(wo0 + px - 1); \
            float y0f = floorf(py), x0f = floorf(pxx); \
            float dy = py - y0f,  dx = pxx - x0f; \
            int y0 = (int)y0f, x0 = (int)x0f; \
            int y1 = y0 + 1,   x1 = x0 + 1; \
            bool vy0 = (y0>=0)&&(y0<H_), vy1 = (y1>=0)&&(y1<H_); \
            bool vx0 = (x0>=0)&&(x0<W_), vx1 = (x1>=0)&&(x1<W_); \
            float* mp = (float*)(sm + SM_META + (BUF)*2048 + px*32); \
            mp[0] = (1.f-dy)*(1.f-dx)*mk * ((vy0&&vx0)?1.f:0.f); \
            mp[1] = (1.f-dy)*dx      *mk * ((vy0&&vx1)?1.f:0.f); \
            mp[2] = dy*(1.f-dx)      *mk * ((vy1&&vx0)?1.f:0.f); \
            mp[3] = dy*dx            *mk * ((vy1&&vx1)?1.f:0.f); \
            int cy0 = min(max(y0,0),H_-1), cy1 = min(max(y1,0),H_-1); \
            int cx0 = min(max(x0,0),W_-1), cx1 = min(max(x1,0),W_-1); \
            ((int*)mp)[4] = (cy0*W_ + cx0) << 8; \
            ((int*)mp)[5] = (cy0*W_ + cx1) << 8; \
            ((int*)mp)[6] = (cy1*W_ + cx0) << 8; \
            ((int*)mp)[7] = (cy1*W_ + cx1) << 8; \
        } \
    } while (0)

    META_FROM_SOM(0, 0);
    __syncthreads();

    float acc[2][2][4];
    #pragma unroll
    for (int m = 0; m < 2; ++m)
        #pragma unroll
        for (int nt = 0; nt < 2; ++nt)
            #pragma unroll
            for (int r = 0; r < 4; ++r) acc[m][nt][r] = 0.f;

    const char* xTb = (const char*)(g_xT + (size_t)b * HW_ * CIN);
    int half = w >> 2;              // 32-ch half
    int pq   = w & 3;               // 16-px group
    int sub  = l >> 3;              // px within 4-group
    int ch4  = l & 7;               // 16B chunk within 128B half-row
    uint32_t chbyte = (uint32_t)(half*128 + ch4*16);

    #pragma unroll 1
    for (int k = 0; k < 9; ++k) {
        if (k) __syncthreads();
        // stage Wd(k) (single buffer; latency hidden under gather)
        {
            uint32_t dst = smb + SM_W + tid*16;
            const char* src = g_Wsplit + k*16384 + tid*16;
            #pragma unroll
            for (int j = 0; j < 4; ++j) CP16(dst + j*4096u, src + j*4096);
            CP_COMMIT();
        }
        // gather tap k -> A (NHWC: LDG.128 = 4px x 1 corner x 4ch)
        {
            const char* mpb = sm + SM_META + (k & 1)*2048;
            #pragma unroll
            for (int g4 = 0; g4 < 4; ++g4) {
                int px = pq*16 + g4*4 + sub;
                const float* mp = (const float*)(mpb + px*32);
                float4 wv = *(const float4*)mp;
                int4   ov = *(const int4*)(mp + 4);
                float4 c00 = *(const float4*)(xTb + (uint32_t)ov.x + chbyte);
                float4 c01 = *(const float4*)(xTb + (uint32_t)ov.y + chbyte);
                float4 c10 = *(const float4*)(xTb + (uint32_t)ov.z + chbyte);
                float4 c11 = *(const float4*)(xTb + (uint32_t)ov.w + chbyte);
                float v0 = wv.x*c00.x + wv.y*c01.x + wv.z*c10.x + wv.w*c11.x;
                float v1 = wv.x*c00.y + wv.y*c01.y + wv.z*c10.y + wv.w*c11.y;
                float v2 = wv.x*c00.z + wv.y*c01.z + wv.z*c10.z + wv.w*c11.z;
                float v3 = wv.x*c00.w + wv.y*c01.w + wv.z*c10.w + wv.w*c11.w;
                uint32_t h0, l0, h1, l1;
                SPLIT2(v0, v1, h0, l0);
                SPLIT2(v2, v3, h1, l1);
                uint32_t sw = sw128((uint32_t)(px*128 + half*64 + ch4*8));
                *(uint2*)(sm + SM_A + sw)        = make_uint2(h0, h1);
                *(uint2*)(sm + SM_A + 8192 + sw) = make_uint2(l0, l1);
            }
        }
        if (k < 8) META_FROM_SOM(k+1, (k+1)&1);
        CP_WAIT(0);
        __syncthreads();

        // GEMM2: 2 m16 x 2 n8, 3 passes
        #pragma unroll
        for (int ks = 0; ks < 4; ++ks) {
            uint32_t ah[2][4], al[2][4], bh[4], bl[4];
            LDMATRIX_X4(ah[0][0],ah[0][1],ah[0][2],ah[0][3], smb + SM_A + aoff[0][ks]);
            LDMATRIX_X4(ah[1][0],ah[1][1],ah[1][2],ah[1][3], smb + SM_A + aoff[1][ks]);
            LDMATRIX_X4(al[0][0],al[0][1],al[0][2],al[0][3], smb + SM_A + 8192u + aoff[0][ks]);
            LDMATRIX_X4(al[1][0],al[1][1],al[1][2],al[1][3], smb + SM_A + 8192u + aoff[1][ks]);
            LDMATRIX_X4(bh[0],bh[1],bh[2],bh[3], smb + SM_W + boff[ks]);
            LDMATRIX_X4(bl[0],bl[1],bl[2],bl[3], smb + SM_W + 8192u + boff[ks]);
            #pragma unroll
            for (int m = 0; m < 2; ++m)
                #pragma unroll
                for (int nt = 0; nt < 2; ++nt) {
                    MMA_BF16(acc[m][nt], ah[m][0],ah[m][1],ah[m][2],ah[m][3], bh[nt*2], bh[nt*2+1]);
                    MMA_BF16(acc[m][nt], al[m][0],al[m][1],al[m][2],al[m][3], bh[nt*2], bh[nt*2+1]);
                    MMA_BF16(acc[m][nt], ah[m][0],ah[m][1],ah[m][2],ah[m][3], bl[nt*2], bl[nt*2+1]);
                }
        }
    }

    // ---- epilogue: transpose via smem (reuse A+W), coalesced store ----
    __syncthreads();
    float* ob = (float*)(sm + SM_A);   // pitch 68 floats, 64*68*4 = 17408B
    int g = l >> 2, tg = l & 3;
    #pragma unroll
    for (int m = 0; m < 2; ++m)
        #pragma unroll
        for (int nt = 0; nt < 2; ++nt) {
            int o  = n4*16 + nt*8 + 2*tg;
            int pa = m2*32 + m*16 + g;
            ob[o*68 + pa]         = acc[m][nt][0];
            ob[(o+1)*68 + pa]     = acc[m][nt][1];
            ob[o*68 + pa + 8]     = acc[m][nt][2];
            ob[(o+1)*68 + pa + 8] = acc[m][nt][3];
        }
    __syncthreads();
    for (int i = tid; i < 64*16; i += 256) {
        int o = i >> 4, seg = i & 15;
        float4 v = *(float4*)&ob[o*68 + seg*4];
        *(float4*)&out[(((size_t)b*CO + o)*HO + ho)*WO + wo0 + seg*4] = v;
    }
}

// ---------------------------------------------------------------------------
extern "C" void kernel_launch(void* const* d_in, const int* in_sizes, int n_in,
                              void* d_out, int out_size) {
    const float* x      = (const float*)d_in[0];
    const float* w_off  = (const float*)d_in[1];
    const float* b_off  = (const float*)d_in[2];
    const float* w_mask = (const float*)d_in[3];
    const float* b_mask = (const float*)d_in[4];
    const float* w_conv = (const float*)d_in[5];
    float* out = (float*)d_out;

    prep_kernel<<<144, 256>>>(w_off, b_off, w_mask, b_mask, w_conv);
    transpose_kernel<<<dim3(4, 128, 8), 256>>>(x);

    cudaFuncSetAttribute((const void*)deform_kernel,
                         cudaFuncAttributeMaxDynamicSharedMemorySize, SM_TOTAL);
    deform_kernel<<<dim3(HO, B_, 2), 256, SM_TOTAL>>>(x, out);
}